// round 16
// baseline (speedup 1.0000x reference)
#include <cuda_runtime.h>
#include <cuda_fp16.h>
#include <cstdint>
#include <math.h>

// ---------------------------------------------------------------------------
// TokenPacker R16: R13 GEMM core exactly (128x128 tile, 16 warps, K=64
// stages, 3-deep cp.async, sector-clean fill, chunk double-buffer) + FLAT
// 1-D job-packed grids (zero dead CTAs; R15's z-padding spawned ~5800 dead
// CTAs each holding a 110KB smem reservation -> ~100us scheduling overhead).
// Job decode is once per CTA (two compares + one div/mod).
// ---------------------------------------------------------------------------

#define E_DIM   1024
#define N_IMG   64
#define NQ_TOK  144
#define TN_TOK  576
#define M_BIG   (N_IMG * TN_TOK)   // 36864
#define M_SMALL (N_IMG * NQ_TOK)   // 9216
#define NST     16                 // K / 64 stages
#define STAGES  3
#define SROW_B  144                // pitch bytes (128B payload + 16 pad)
#define BM      128
#define BN      128
#define STAGE_B ((BM + BN) * SROW_B)   // 36864
#define MW      (1024 * 1024)

// Scratch (device statics; no cudaMalloc allowed)
__device__ __align__(256) __half g_h2 [(size_t)M_BIG * 2048];   // gelu(K1|V1)
__device__ __align__(256) __half g_key[(size_t)M_BIG   * E_DIM];
__device__ __align__(256) __half g_val[(size_t)M_BIG   * E_DIM];
__device__ __align__(256) __half g_kh [(size_t)M_BIG   * E_DIM];
__device__ __align__(256) __half g_vh [(size_t)M_BIG   * E_DIM];
__device__ __align__(256) __half g_q  [(size_t)M_SMALL * E_DIM];
__device__ __align__(256) __half g_qh [(size_t)M_SMALL * E_DIM];
__device__ __align__(256) __half g_o  [(size_t)M_SMALL * E_DIM];
__device__ __align__(256) __half g_xr [(size_t)M_SMALL * E_DIM];
__device__ __align__(256) __half g_xfr[(size_t)M_BIG   * E_DIM];
__device__ __align__(256) __half g_wt [9ull * 1024 * 1024];
__device__ __align__(256) float  g_bcat[2048];

__device__ __forceinline__ float gelu_exact(float x) {
    return 0.5f * x * (1.0f + erff(x * 0.70710678118654752f));
}

#define CP_ASYNC16(smem_u32a, gptr) \
    asm volatile("cp.async.cg.shared.global [%0], [%1], 16;\n" :: "r"(smem_u32a), "l"(gptr))

#define LDSM_X4(r0, r1, r2, r3, addr) \
    asm volatile("ldmatrix.sync.aligned.m8n8.x4.shared.b16 {%0,%1,%2,%3}, [%4];" \
                 : "=r"(r0), "=r"(r1), "=r"(r2), "=r"(r3) : "r"(addr))

#define MMA16816(d, a, b) \
    asm volatile("mma.sync.aligned.m16n8k16.row.col.f32.f16.f16.f32 " \
                 "{%0,%1,%2,%3}, {%4,%5,%6,%7}, {%8,%9}, {%0,%1,%2,%3};\n" \
                 : "+f"((d)[0]), "+f"((d)[1]), "+f"((d)[2]), "+f"((d)[3]) \
                 : "r"((a)[0]), "r"((a)[1]), "r"((a)[2]), "r"((a)[3]), \
                   "r"((b)[0]), "r"((b)[1]))

// ---------------------------------------------------------------------------
// Merged f32 -> f16 conversion prepass
// ---------------------------------------------------------------------------
struct ConvJob { const float4* src; __half2* dst; int n4; };
struct ConvJobs { ConvJob j[9]; };

__global__ void conv_all_kernel(ConvJobs jobs)
{
    const ConvJob jb = jobs.j[blockIdx.y];
    for (int i = blockIdx.x * blockDim.x + threadIdx.x; i < jb.n4;
         i += gridDim.x * blockDim.x) {
        float4 v = jb.src[i];
        jb.dst[2 * i]     = __floats2half2_rn(v.x, v.y);
        jb.dst[2 * i + 1] = __floats2half2_rn(v.z, v.w);
    }
}

__global__ void bias_concat_kernel(const float* __restrict__ b0,
                                   const float* __restrict__ b1,
                                   float* __restrict__ out)
{
    int i = blockIdx.x * blockDim.x + threadIdx.x;
    out[i] = (i < 1024) ? b0[i] : b1[i - 1024];
}

// ---------------------------------------------------------------------------
// Flat job-packed GEMM: 1-D grid over sum of per-job tile counts (no dead
// CTAs). Per job: C[? x N] = act(A[? x 1024] @ W[N x 1024]^T + bias).
// Inner loop identical to R13.
// ---------------------------------------------------------------------------
struct GJobs {
    const __half* A[3];
    const __half* W[3];
    const float*  bias[3];
    void*         C[3];
    int lda[3];
    int ldc[3];
    int ntx[3];      // x tiles (N/128)
    int cnt[3];      // tiles in job (ntx*nty)
    int actmask;     // bit z: GELU epilogue
    int outfmask;    // bit z: float output
};

__global__ __launch_bounds__(256, 2)
void gemm_f16(GJobs j)
{
    extern __shared__ __align__(128) char smem[];
    uint32_t sb;
    asm("{ .reg .u64 t; cvta.to.shared.u64 t, %1; cvt.u32.u64 %0, t; }" : "=r"(sb) : "l"(smem));

    // flat tile decode (once per CTA)
    int t = blockIdx.x;
    int z = 0;
    if (t >= j.cnt[0]) { t -= j.cnt[0]; z = 1; }
    if (z == 1 && t >= j.cnt[1]) { t -= j.cnt[1]; z = 2; }
    const int ntx = j.ntx[z];
    const int ty  = t / ntx;
    const int tx  = t - ty * ntx;

    const __half* A   = j.A[z];
    const __half* W   = j.W[z];
    const float* bias = j.bias[z];
    void* Cv          = j.C[z];
    const int lda     = j.lda[z];
    const int ldc     = j.ldc[z];
    const bool act    = (j.actmask >> z) & 1;
    const bool outf   = (j.outfmask >> z) & 1;

    const int tid  = threadIdx.x;
    const int warp = tid >> 5;
    const int lane = tid & 31;
    const int grp  = lane >> 2;
    const int tig  = lane & 3;
    const int wm   = (warp & 1) * 64;
    const int wn   = (warp >> 1) * 32;
    const int row0 = ty * BM;
    const int col0 = tx * BN;

    float acc[4][4][4];
    #pragma unroll
    for (int i = 0; i < 4; i++)
        #pragma unroll
        for (int jj = 0; jj < 4; jj++)
            #pragma unroll
            for (int k = 0; k < 4; k++) acc[i][jj][k] = 0.0f;

    const int lg  = lane >> 3;
    const int lr8 = lane & 7;
    uint32_t aoff[4];
    #pragma unroll
    for (int mi = 0; mi < 4; mi++)
        aoff[mi] = (uint32_t)((wm + mi * 16 + (lg & 1) * 8 + lr8) * SROW_B + (lg >> 1) * 16);
    uint32_t boff[2];
    #pragma unroll
    for (int jj = 0; jj < 2; jj++)
        boff[jj] = (uint32_t)((BM + wn + (jj * 2 + (lg >> 1)) * 8 + lr8) * SROW_B + (lg & 1) * 16);

    // sector-clean fill: 8 lanes x 16B = 128B contiguous per row
    const int fr0 = tid >> 3;
    const int fc  = (tid & 7) * 16;   // bytes
    const __half* Ag = A + (size_t)(row0 + fr0) * lda + fc / 2;
    const __half* Wg = W + (size_t)(col0 + fr0) * E_DIM + fc / 2;
    const uint32_t aD = sb + fr0 * SROW_B + fc;
    const uint32_t bD = sb + (BM + fr0) * SROW_B + fc;

    #pragma unroll
    for (int st = 0; st < 2; st++) {
        const int ko = st * 64;   // halves
        #pragma unroll
        for (int i = 0; i < 4; i++) {
            CP_ASYNC16(aD + st * STAGE_B + i * 32 * SROW_B, Ag + (size_t)i * 32 * lda + ko);
            CP_ASYNC16(bD + st * STAGE_B + i * 32 * SROW_B, Wg + (size_t)i * 32 * E_DIM + ko);
        }
        asm volatile("cp.async.commit_group;\n");
    }

    int slot = 0;
    for (int it = 0; it < NST; it++) {
        asm volatile("cp.async.wait_group 1;\n");
        __syncthreads();

        const uint32_t stage = sb + slot * STAGE_B;

        // chunk0 fragments first (latency under fill issue)
        uint32_t af[2][4][4], bf[2][4][2];
        #pragma unroll
        for (int mi = 0; mi < 4; mi++)
            LDSM_X4(af[0][mi][0], af[0][mi][1], af[0][mi][2], af[0][mi][3], stage + aoff[mi]);
        #pragma unroll
        for (int jj = 0; jj < 2; jj++)
            LDSM_X4(bf[0][jj * 2][0], bf[0][jj * 2][1],
                    bf[0][jj * 2 + 1][0], bf[0][jj * 2 + 1][1], stage + boff[jj]);

        const int pf = it + 2;
        if (pf < NST) {
            const int s = (slot + 2 >= STAGES) ? slot + 2 - STAGES : slot + 2;
            const int ko = pf * 64;
            #pragma unroll
            for (int i = 0; i < 4; i++) {
                CP_ASYNC16(aD + s * STAGE_B + i * 32 * SROW_B, Ag + (size_t)i * 32 * lda + ko);
                CP_ASYNC16(bD + s * STAGE_B + i * 32 * SROW_B, Wg + (size_t)i * 32 * E_DIM + ko);
            }
        }
        asm volatile("cp.async.commit_group;\n");

        #pragma unroll
        for (int c = 0; c < 4; c++) {
            const int cur = c & 1, nxt = cur ^ 1;
            if (c < 3) {
                const uint32_t co = (uint32_t)(c + 1) * 32;
                #pragma unroll
                for (int mi = 0; mi < 4; mi++)
                    LDSM_X4(af[nxt][mi][0], af[nxt][mi][1], af[nxt][mi][2], af[nxt][mi][3],
                            stage + aoff[mi] + co);
                #pragma unroll
                for (int jj = 0; jj < 2; jj++)
                    LDSM_X4(bf[nxt][jj * 2][0], bf[nxt][jj * 2][1],
                            bf[nxt][jj * 2 + 1][0], bf[nxt][jj * 2 + 1][1],
                            stage + boff[jj] + co);
            }
            #pragma unroll
            for (int mi = 0; mi < 4; mi++)
                #pragma unroll
                for (int ni = 0; ni < 4; ni++)
                    MMA16816(acc[mi][ni], af[cur][mi], bf[cur][ni]);
        }

        slot = (slot + 1 >= STAGES) ? 0 : slot + 1;
    }

    // epilogue
    #pragma unroll
    for (int ni = 0; ni < 4; ni++) {
        const int col = col0 + wn + ni * 8 + tig * 2;
        float bv0 = 0.0f, bv1 = 0.0f;
        if (bias) { bv0 = bias[col]; bv1 = bias[col + 1]; }
        #pragma unroll
        for (int mi = 0; mi < 4; mi++) {
            #pragma unroll
            for (int half_ = 0; half_ < 2; half_++) {
                const int row = row0 + wm + mi * 16 + grp + half_ * 8;
                float v0 = acc[mi][ni][half_ * 2 + 0] + bv0;
                float v1 = acc[mi][ni][half_ * 2 + 1] + bv1;
                if (act) { v0 = gelu_exact(v0); v1 = gelu_exact(v1); }
                if (outf) {
                    *(float2*)((float*)Cv + (size_t)row * ldc + col) = make_float2(v0, v1);
                } else {
                    *(__half2*)((__half*)Cv + (size_t)row * ldc + col) = __floats2half2_rn(v0, v1);
                }
            }
        }
    }
}

// ---------------------------------------------------------------------------
// Multi-job in-place LayerNorm (3 jobs; rows of 1024 halves, eps=1e-6)
// ---------------------------------------------------------------------------
struct LnJobs { __half* d[3]; const float* w[3]; const float* b[3]; int rows[3]; };

__global__ void ln3_kernel(LnJobs jb)
{
    int r = blockIdx.x;
    int job = 0;
    if (r >= jb.rows[0]) { r -= jb.rows[0]; job = 1; }
    if (job == 1 && r >= jb.rows[1]) { r -= jb.rows[1]; job = 2; }
    __half* data = jb.d[job];
    const float* w = jb.w[job];
    const float* b = jb.b[job];

    __half2* p = (__half2*)(data + (size_t)r * E_DIM);
    const __half2 h0 = p[2 * threadIdx.x], h1 = p[2 * threadIdx.x + 1];
    float2 f0 = __half22float2(h0), f1 = __half22float2(h1);
    float s = f0.x + f0.y + f1.x + f1.y;
    float q = f0.x * f0.x + f0.y * f0.y + f1.x * f1.x + f1.y * f1.y;
    #pragma unroll
    for (int o = 16; o; o >>= 1) {
        s += __shfl_xor_sync(0xffffffffu, s, o);
        q += __shfl_xor_sync(0xffffffffu, q, o);
    }
    __shared__ float ss[8], sq[8];
    const int warp = threadIdx.x >> 5, lane = threadIdx.x & 31;
    if (lane == 0) { ss[warp] = s; sq[warp] = q; }
    __syncthreads();
    if (warp == 0) {
        s = (lane < 8) ? ss[lane] : 0.0f;
        q = (lane < 8) ? sq[lane] : 0.0f;
        #pragma unroll
        for (int o = 4; o; o >>= 1) {
            s += __shfl_xor_sync(0xffffffffu, s, o);
            q += __shfl_xor_sync(0xffffffffu, q, o);
        }
        if (lane == 0) { ss[0] = s; sq[0] = q; }
    }
    __syncthreads();
    const float mean = ss[0] * (1.0f / 1024.0f);
    const float var  = sq[0] * (1.0f / 1024.0f) - mean * mean;
    const float rstd = rsqrtf(var + 1e-6f);
    const float4 wv = ((const float4*)w)[threadIdx.x];
    const float4 bv = ((const float4*)b)[threadIdx.x];
    p[2 * threadIdx.x] = __floats2half2_rn((f0.x - mean) * rstd * wv.x + bv.x,
                                           (f0.y - mean) * rstd * wv.y + bv.y);
    p[2 * threadIdx.x + 1] = __floats2half2_rn((f1.x - mean) * rstd * wv.z + bv.z,
                                               (f1.y - mean) * rstd * wv.w + bv.w);
}

// ---------------------------------------------------------------------------
// Attention: q len 1 over 2x2 key patch. fp16 in/out, fp32 math.
// ---------------------------------------------------------------------------
__global__ void attn_kernel(const __half* __restrict__ qh, const __half* __restrict__ kh,
                            const __half* __restrict__ vh, __half* __restrict__ o)
{
    const int r  = blockIdx.x;
    const int n  = r / NQ_TOK;
    const int qi = r - n * NQ_TOK;
    const int ar = qi / 12;
    const int ac = qi - ar * 12;
    const int head = threadIdx.x >> 5, lane = threadIdx.x & 31;
    const size_t qoff = (size_t)r * E_DIM + head * 128 + lane * 4;
    const __half2* qp = (const __half2*)(qh + qoff);
    const float2 q0 = __half22float2(qp[0]), q1 = __half22float2(qp[1]);

    int trow[4];
    #pragma unroll
    for (int j = 0; j < 4; j++)
        trow[j] = n * TN_TOK + (2 * ar + (j >> 1)) * 24 + (2 * ac + (j & 1));

    float s[4];
    #pragma unroll
    for (int j = 0; j < 4; j++) {
        const __half2* kp = (const __half2*)(kh + (size_t)trow[j] * E_DIM + head * 128 + lane * 4);
        const float2 k0 = __half22float2(kp[0]), k1 = __half22float2(kp[1]);
        float d = q0.x * k0.x + q0.y * k0.y + q1.x * k1.x + q1.y * k1.y;
        #pragma unroll
        for (int off = 16; off; off >>= 1) d += __shfl_xor_sync(0xffffffffu, d, off);
        s[j] = d * 0.08838834764831843f;
    }
    const float m = fmaxf(fmaxf(s[0], s[1]), fmaxf(s[2], s[3]));
    float e[4], tot = 0.0f;
    #pragma unroll
    for (int j = 0; j < 4; j++) { e[j] = expf(s[j] - m); tot += e[j]; }
    const float inv = 1.0f / tot;

    float a0 = 0.f, a1 = 0.f, a2 = 0.f, a3 = 0.f;
    #pragma unroll
    for (int j = 0; j < 4; j++) {
        const float pj = e[j] * inv;
        const __half2* vp = (const __half2*)(vh + (size_t)trow[j] * E_DIM + head * 128 + lane * 4);
        const float2 v0 = __half22float2(vp[0]), v1 = __half22float2(vp[1]);
        a0 += pj * v0.x; a1 += pj * v0.y; a2 += pj * v1.x; a3 += pj * v1.y;
    }
    __half2* op = (__half2*)(o + qoff);
    op[0] = __floats2half2_rn(a0, a1);
    op[1] = __floats2half2_rn(a2, a3);
}

// ---------------------------------------------------------------------------
extern "C" void kernel_launch(void* const* d_in, const int* in_sizes, int n_in,
                              void* d_out, int out_size)
{
    const float* x      = (const float*)d_in[0];
    const float* x_feat = (const float*)d_in[1];
    const float* w_q    = (const float*)d_in[2];
    const float* w_k1   = (const float*)d_in[3];
    const float* b_k1   = (const float*)d_in[4];
    const float* w_k2   = (const float*)d_in[5];
    const float* b_k2   = (const float*)d_in[6];
    const float* w_v1   = (const float*)d_in[7];
    const float* b_v1   = (const float*)d_in[8];
    const float* w_v2   = (const float*)d_in[9];
    const float* b_v2   = (const float*)d_in[10];
    const float* ln_q_w = (const float*)d_in[11];
    const float* ln_q_b = (const float*)d_in[12];
    const float* ln_k_w = (const float*)d_in[13];
    const float* ln_k_b = (const float*)d_in[14];
    const float* ln_v_w = (const float*)d_in[15];
    const float* ln_v_b = (const float*)d_in[16];
    const float* in_w   = (const float*)d_in[17];
    const float* in_b   = (const float*)d_in[18];
    const float* out_w  = (const float*)d_in[19];
    const float* out_b  = (const float*)d_in[20];

    __half *h2, *key, *val, *kh, *vh, *qb, *qh, *o, *xr, *xfr, *wt;
    float* bcat;
    cudaGetSymbolAddress((void**)&h2,  g_h2);
    cudaGetSymbolAddress((void**)&key, g_key);
    cudaGetSymbolAddress((void**)&val, g_val);
    cudaGetSymbolAddress((void**)&kh,  g_kh);
    cudaGetSymbolAddress((void**)&vh,  g_vh);
    cudaGetSymbolAddress((void**)&qb,  g_q);
    cudaGetSymbolAddress((void**)&qh,  g_qh);
    cudaGetSymbolAddress((void**)&o,   g_o);
    cudaGetSymbolAddress((void**)&xr,  g_xr);
    cudaGetSymbolAddress((void**)&xfr, g_xfr);
    cudaGetSymbolAddress((void**)&wt,  g_wt);
    cudaGetSymbolAddress((void**)&bcat, g_bcat);

    __half* wt_kv1 = wt;                    // [w_k1 ; w_v1]
    __half* wt_k2  = wt + 2 * (size_t)MW;   // wt_v2 contiguous at +MW
    __half* wt_q   = wt + 4 * (size_t)MW;
    __half* wt_in  = wt + 5 * (size_t)MW;   // wqh | wkh | wvh
    __half* wt_out = wt + 8 * (size_t)MW;

    const int smem_bytes = STAGES * STAGE_B;  // 110592
    cudaFuncSetAttribute(gemm_f16, cudaFuncAttributeMaxDynamicSharedMemorySize, smem_bytes);

    // launch 1: merged conversion prepass
    {
        ConvJobs jobs;
        jobs.j[0] = { (const float4*)x,      (__half2*)xr,      M_SMALL * E_DIM / 4 };
        jobs.j[1] = { (const float4*)x_feat, (__half2*)xfr,     M_BIG   * E_DIM / 4 };
        jobs.j[2] = { (const float4*)w_k1,   (__half2*)wt_kv1,  MW / 4 };
        jobs.j[3] = { (const float4*)w_v1,   (__half2*)(wt_kv1 + MW), MW / 4 };
        jobs.j[4] = { (const float4*)w_k2,   (__half2*)wt_k2,   MW / 4 };
        jobs.j[5] = { (const float4*)w_v2,   (__half2*)(wt_k2 + MW), MW / 4 };
        jobs.j[6] = { (const float4*)w_q,    (__half2*)wt_q,    MW / 4 };
        jobs.j[7] = { (const float4*)in_w,   (__half2*)wt_in,   3 * MW / 4 };
        jobs.j[8] = { (const float4*)out_w,  (__half2*)wt_out,  MW / 4 };
        conv_all_kernel<<<dim3(4096, 9), 256>>>(jobs);
    }
    // launch 2: bias concat
    bias_concat_kernel<<<8, 256>>>(b_k1, b_v1, bcat);

    const dim3 blk(256);
    const int TB = M_BIG / BM;     // 288 y-tiles
    const int TS = M_SMALL / BM;   // 72 y-tiles

    // launch 3: KV1 (gelu, 16x288 tiles) + qb (8x72 tiles) -- flat packed
    {
        GJobs gj = {};
        gj.A[0] = xfr; gj.W[0] = wt_kv1; gj.bias[0] = bcat;    gj.C[0] = h2;
        gj.lda[0] = E_DIM; gj.ldc[0] = 2048; gj.ntx[0] = 16; gj.cnt[0] = 16 * TB;
        gj.A[1] = xr;  gj.W[1] = wt_q;   gj.bias[1] = nullptr; gj.C[1] = qb;
        gj.lda[1] = E_DIM; gj.ldc[1] = E_DIM; gj.ntx[1] = 8; gj.cnt[1] = 8 * TS;
        gj.actmask = 0x1; gj.outfmask = 0;
        gemm_f16<<<16 * TB + 8 * TS, blk, smem_bytes>>>(gj);   // 5184
    }
    // launch 4 (ncu capture slot): K2 + V2 -- flat packed
    {
        GJobs gj = {};
        gj.A[0] = h2;        gj.W[0] = wt_k2;      gj.bias[0] = b_k2; gj.C[0] = key;
        gj.lda[0] = 2048; gj.ldc[0] = E_DIM; gj.ntx[0] = 8; gj.cnt[0] = 8 * TB;
        gj.A[1] = h2 + 1024; gj.W[1] = wt_k2 + MW; gj.bias[1] = b_v2; gj.C[1] = val;
        gj.lda[1] = 2048; gj.ldc[1] = E_DIM; gj.ntx[1] = 8; gj.cnt[1] = 8 * TB;
        gj.actmask = 0; gj.outfmask = 0;
        gemm_f16<<<16 * TB, blk, smem_bytes>>>(gj);            // 4608
    }
    // launch 5: 3-job LN (key, val, qb)
    {
        LnJobs lj = {};
        lj.d[0] = key; lj.w[0] = ln_k_w; lj.b[0] = ln_k_b; lj.rows[0] = M_BIG;
        lj.d[1] = val; lj.w[1] = ln_v_w; lj.b[1] = ln_v_b; lj.rows[1] = M_BIG;
        lj.d[2] = qb;  lj.w[2] = ln_q_w; lj.b[2] = ln_q_b; lj.rows[2] = M_SMALL;
        ln3_kernel<<<2 * M_BIG + M_SMALL, 256>>>(lj);
    }
    // launch 6: in_proj qh + kh + vh -- flat packed
    {
        GJobs gj = {};
        gj.A[0] = qb;  gj.W[0] = wt_in;          gj.bias[0] = in_b;        gj.C[0] = qh;
        gj.lda[0] = E_DIM; gj.ldc[0] = E_DIM; gj.ntx[0] = 8; gj.cnt[0] = 8 * TS;
        gj.A[1] = key; gj.W[1] = wt_in + MW;     gj.bias[1] = in_b + 1024; gj.C[1] = kh;
        gj.lda[1] = E_DIM; gj.ldc[1] = E_DIM; gj.ntx[1] = 8; gj.cnt[1] = 8 * TB;
        gj.A[2] = val; gj.W[2] = wt_in + 2 * MW; gj.bias[2] = in_b + 2048; gj.C[2] = vh;
        gj.lda[2] = E_DIM; gj.ldc[2] = E_DIM; gj.ntx[2] = 8; gj.cnt[2] = 8 * TB;
        gj.actmask = 0; gj.outfmask = 0;
        gemm_f16<<<8 * TS + 16 * TB, blk, smem_bytes>>>(gj);   // 5184
    }
    // launch 7: attention
    attn_kernel<<<M_SMALL, 256>>>(qh, kh, vh, o);
    // launch 8: out_proj -> d_out (float)
    {
        GJobs gj = {};
        gj.A[0] = o; gj.W[0] = wt_out; gj.bias[0] = out_b; gj.C[0] = d_out;
        gj.lda[0] = E_DIM; gj.ldc[0] = E_DIM; gj.ntx[0] = 8; gj.cnt[0] = 8 * TS;
        gj.actmask = 0; gj.outfmask = 0x1;
        gemm_f16<<<8 * TS, blk, smem_bytes>>>(gj);             // 576
    }
}

// round 17
// speedup vs baseline: 1.1016x; 1.1016x over previous
#include <cuda_runtime.h>
#include <cuda_fp16.h>
#include <cstdint>
#include <math.h>

// ---------------------------------------------------------------------------
// TokenPacker R17: R13 verbatim (GEMM core + dual-z launch structure; best =
// 1814us) + warp-per-row LayerNorm (R6 profile showed LN at DRAM=22.7%,
// issue=57.6% -> latency/sync-bound; warp-per-row removes all __syncthreads)
// merged into ONE 3-job LN launch. R15/R16 launch-packing rewrites reverted.
// ---------------------------------------------------------------------------

#define E_DIM   1024
#define N_IMG   64
#define NQ_TOK  144
#define TN_TOK  576
#define M_BIG   (N_IMG * TN_TOK)   // 36864
#define M_SMALL (N_IMG * NQ_TOK)   // 9216
#define NST     16                 // K / 64 stages
#define STAGES  3
#define SROW_B  144                // pitch bytes (128B payload + 16 pad)
#define BM      128
#define BN      128
#define STAGE_B ((BM + BN) * SROW_B)   // 36864
#define MW      (1024 * 1024)

// Scratch (device statics; no cudaMalloc allowed)
__device__ __align__(256) __half g_h2 [(size_t)M_BIG * 2048];   // gelu(K1|V1)
__device__ __align__(256) __half g_key[(size_t)M_BIG   * E_DIM];
__device__ __align__(256) __half g_val[(size_t)M_BIG   * E_DIM];
__device__ __align__(256) __half g_kh [(size_t)M_BIG   * E_DIM];
__device__ __align__(256) __half g_vh [(size_t)M_BIG   * E_DIM];
__device__ __align__(256) __half g_q  [(size_t)M_SMALL * E_DIM];
__device__ __align__(256) __half g_qh [(size_t)M_SMALL * E_DIM];
__device__ __align__(256) __half g_o  [(size_t)M_SMALL * E_DIM];
__device__ __align__(256) __half g_xr [(size_t)M_SMALL * E_DIM];
__device__ __align__(256) __half g_xfr[(size_t)M_BIG   * E_DIM];
__device__ __align__(256) __half g_wt [9ull * 1024 * 1024];
__device__ __align__(256) float  g_bcat[2048];

__device__ __forceinline__ float gelu_exact(float x) {
    return 0.5f * x * (1.0f + erff(x * 0.70710678118654752f));
}

#define CP_ASYNC16(smem_u32a, gptr) \
    asm volatile("cp.async.cg.shared.global [%0], [%1], 16;\n" :: "r"(smem_u32a), "l"(gptr))

#define LDSM_X4(r0, r1, r2, r3, addr) \
    asm volatile("ldmatrix.sync.aligned.m8n8.x4.shared.b16 {%0,%1,%2,%3}, [%4];" \
                 : "=r"(r0), "=r"(r1), "=r"(r2), "=r"(r3) : "r"(addr))

#define MMA16816(d, a, b) \
    asm volatile("mma.sync.aligned.m16n8k16.row.col.f32.f16.f16.f32 " \
                 "{%0,%1,%2,%3}, {%4,%5,%6,%7}, {%8,%9}, {%0,%1,%2,%3};\n" \
                 : "+f"((d)[0]), "+f"((d)[1]), "+f"((d)[2]), "+f"((d)[3]) \
                 : "r"((a)[0]), "r"((a)[1]), "r"((a)[2]), "r"((a)[3]), \
                   "r"((b)[0]), "r"((b)[1]))

// ---------------------------------------------------------------------------
// Merged f32 -> f16 conversion prepass
// ---------------------------------------------------------------------------
struct ConvJob { const float4* src; __half2* dst; int n4; };
struct ConvJobs { ConvJob j[9]; };

__global__ void conv_all_kernel(ConvJobs jobs)
{
    const ConvJob jb = jobs.j[blockIdx.y];
    for (int i = blockIdx.x * blockDim.x + threadIdx.x; i < jb.n4;
         i += gridDim.x * blockDim.x) {
        float4 v = jb.src[i];
        jb.dst[2 * i]     = __floats2half2_rn(v.x, v.y);
        jb.dst[2 * i + 1] = __floats2half2_rn(v.z, v.w);
    }
}

__global__ void bias_concat_kernel(const float* __restrict__ b0,
                                   const float* __restrict__ b1,
                                   float* __restrict__ out)
{
    int i = blockIdx.x * blockDim.x + threadIdx.x;
    out[i] = (i < 1024) ? b0[i] : b1[i - 1024];
}

// ---------------------------------------------------------------------------
// GEMM (dual-job via blockIdx.z): C[M x N] = act(A @ W^T + bias)
// R13 core: 128x128 tile, 8 warps of 64x32, K=64 stages, 3-deep cp.async,
// sector-clean fill, chunk double-buffer, chunk0-LDSM-before-fill.
// ---------------------------------------------------------------------------
template <int ACT, int OUTF>
__global__ __launch_bounds__(256, 2)
void gemm_f16(const __half* __restrict__ A0, const __half* __restrict__ A1, int lda,
              const __half* __restrict__ W0,
              const float* __restrict__ bias0, const float* __restrict__ bias1,
              void* __restrict__ C0, void* __restrict__ C1, int ldc)
{
    extern __shared__ __align__(128) char smem[];
    uint32_t sb;
    asm("{ .reg .u64 t; cvta.to.shared.u64 t, %1; cvt.u32.u64 %0, t; }" : "=r"(sb) : "l"(smem));

    const int z = blockIdx.z;
    const __half* A   = z ? A1 : A0;
    const __half* W   = W0 + (size_t)z * MW;
    const float* bias = z ? bias1 : bias0;
    void* Cv          = z ? C1 : C0;

    const int tid  = threadIdx.x;
    const int warp = tid >> 5;
    const int lane = tid & 31;
    const int grp  = lane >> 2;
    const int tig  = lane & 3;
    const int wm   = (warp & 1) * 64;
    const int wn   = (warp >> 1) * 32;
    const int row0 = blockIdx.y * BM;
    const int col0 = blockIdx.x * BN;

    float acc[4][4][4];
    #pragma unroll
    for (int i = 0; i < 4; i++)
        #pragma unroll
        for (int jj = 0; jj < 4; jj++)
            #pragma unroll
            for (int k = 0; k < 4; k++) acc[i][jj][k] = 0.0f;

    const int lg  = lane >> 3;
    const int lr8 = lane & 7;
    uint32_t aoff[4];
    #pragma unroll
    for (int mi = 0; mi < 4; mi++)
        aoff[mi] = (uint32_t)((wm + mi * 16 + (lg & 1) * 8 + lr8) * SROW_B + (lg >> 1) * 16);
    uint32_t boff[2];
    #pragma unroll
    for (int jj = 0; jj < 2; jj++)
        boff[jj] = (uint32_t)((BM + wn + (jj * 2 + (lg >> 1)) * 8 + lr8) * SROW_B + (lg & 1) * 16);

    // sector-clean fill: 8 lanes x 16B = 128B contiguous per row
    const int fr0 = tid >> 3;
    const int fc  = (tid & 7) * 16;   // bytes
    const __half* Ag = A + (size_t)(row0 + fr0) * lda + fc / 2;
    const __half* Wg = W + (size_t)(col0 + fr0) * E_DIM + fc / 2;
    const uint32_t aD = sb + fr0 * SROW_B + fc;
    const uint32_t bD = sb + (BM + fr0) * SROW_B + fc;

    #pragma unroll
    for (int st = 0; st < 2; st++) {
        const int ko = st * 64;   // halves
        #pragma unroll
        for (int i = 0; i < 4; i++) {
            CP_ASYNC16(aD + st * STAGE_B + i * 32 * SROW_B, Ag + (size_t)i * 32 * lda + ko);
            CP_ASYNC16(bD + st * STAGE_B + i * 32 * SROW_B, Wg + (size_t)i * 32 * E_DIM + ko);
        }
        asm volatile("cp.async.commit_group;\n");
    }

    int slot = 0;
    for (int it = 0; it < NST; it++) {
        asm volatile("cp.async.wait_group 1;\n");
        __syncthreads();

        const uint32_t stage = sb + slot * STAGE_B;

        // chunk0 fragments first (latency under fill issue)
        uint32_t af[2][4][4], bf[2][4][2];
        #pragma unroll
        for (int mi = 0; mi < 4; mi++)
            LDSM_X4(af[0][mi][0], af[0][mi][1], af[0][mi][2], af[0][mi][3], stage + aoff[mi]);
        #pragma unroll
        for (int jj = 0; jj < 2; jj++)
            LDSM_X4(bf[0][jj * 2][0], bf[0][jj * 2][1],
                    bf[0][jj * 2 + 1][0], bf[0][jj * 2 + 1][1], stage + boff[jj]);

        const int pf = it + 2;
        if (pf < NST) {
            const int s = (slot + 2 >= STAGES) ? slot + 2 - STAGES : slot + 2;
            const int ko = pf * 64;
            #pragma unroll
            for (int i = 0; i < 4; i++) {
                CP_ASYNC16(aD + s * STAGE_B + i * 32 * SROW_B, Ag + (size_t)i * 32 * lda + ko);
                CP_ASYNC16(bD + s * STAGE_B + i * 32 * SROW_B, Wg + (size_t)i * 32 * E_DIM + ko);
            }
        }
        asm volatile("cp.async.commit_group;\n");

        #pragma unroll
        for (int c = 0; c < 4; c++) {
            const int cur = c & 1, nxt = cur ^ 1;
            if (c < 3) {
                const uint32_t co = (uint32_t)(c + 1) * 32;
                #pragma unroll
                for (int mi = 0; mi < 4; mi++)
                    LDSM_X4(af[nxt][mi][0], af[nxt][mi][1], af[nxt][mi][2], af[nxt][mi][3],
                            stage + aoff[mi] + co);
                #pragma unroll
                for (int jj = 0; jj < 2; jj++)
                    LDSM_X4(bf[nxt][jj * 2][0], bf[nxt][jj * 2][1],
                            bf[nxt][jj * 2 + 1][0], bf[nxt][jj * 2 + 1][1],
                            stage + boff[jj] + co);
            }
            #pragma unroll
            for (int mi = 0; mi < 4; mi++)
                #pragma unroll
                for (int ni = 0; ni < 4; ni++)
                    MMA16816(acc[mi][ni], af[cur][mi], bf[cur][ni]);
        }

        slot = (slot + 1 >= STAGES) ? 0 : slot + 1;
    }

    // epilogue
    #pragma unroll
    for (int ni = 0; ni < 4; ni++) {
        const int col = col0 + wn + ni * 8 + tig * 2;
        float bv0 = 0.0f, bv1 = 0.0f;
        if (bias) { bv0 = bias[col]; bv1 = bias[col + 1]; }
        #pragma unroll
        for (int mi = 0; mi < 4; mi++) {
            #pragma unroll
            for (int half_ = 0; half_ < 2; half_++) {
                const int row = row0 + wm + mi * 16 + grp + half_ * 8;
                float v0 = acc[mi][ni][half_ * 2 + 0] + bv0;
                float v1 = acc[mi][ni][half_ * 2 + 1] + bv1;
                if (ACT == 1) { v0 = gelu_exact(v0); v1 = gelu_exact(v1); }
                if (OUTF) {
                    *(float2*)((float*)Cv + (size_t)row * ldc + col) = make_float2(v0, v1);
                } else {
                    *(__half2*)((__half*)Cv + (size_t)row * ldc + col) = __floats2half2_rn(v0, v1);
                }
            }
        }
    }
}

// ---------------------------------------------------------------------------
// Warp-per-row LayerNorm, 3 jobs in one launch. 8 rows per 256-thread block,
// no __syncthreads, no smem. Row = 1024 halves = 128 float4; lane handles
// float4 indices {lane, lane+32, lane+64, lane+96} (sector-dense loads).
// ---------------------------------------------------------------------------
struct LnJobs { __half* d[3]; const float* w[3]; const float* b[3]; int rows[3]; };

__global__ void ln3_kernel(LnJobs jb)
{
    const int warp = threadIdx.x >> 5, lane = threadIdx.x & 31;
    int r = blockIdx.x * 8 + warp;
    int job = 0;
    if (r >= jb.rows[0]) { r -= jb.rows[0]; job = 1; }
    if (job == 1 && r >= jb.rows[1]) { r -= jb.rows[1]; job = 2; }

    float4* p4 = (float4*)(jb.d[job] + (size_t)r * E_DIM);   // 128 float4/row
    const float4* wp = (const float4*)jb.w[job];             // 256 float4
    const float4* bp = (const float4*)jb.b[job];

    float4 v[4];
    float s = 0.0f, q = 0.0f;
    #pragma unroll
    for (int i = 0; i < 4; i++) {
        v[i] = p4[lane + 32 * i];
        const __half2* h = (const __half2*)&v[i];
        #pragma unroll
        for (int k = 0; k < 4; k++) {
            float2 f = __half22float2(h[k]);
            s += f.x + f.y;
            q += f.x * f.x + f.y * f.y;
        }
    }
    #pragma unroll
    for (int o = 16; o; o >>= 1) {
        s += __shfl_xor_sync(0xffffffffu, s, o);
        q += __shfl_xor_sync(0xffffffffu, q, o);
    }
    const float mean = s * (1.0f / 1024.0f);
    const float var  = q * (1.0f / 1024.0f) - mean * mean;
    const float rstd = rsqrtf(var + 1e-6f);

    #pragma unroll
    for (int i = 0; i < 4; i++) {
        const int f4 = lane + 32 * i;        // float4-of-halves index (8 halves)
        const float4 w0 = wp[f4 * 2],     w1 = wp[f4 * 2 + 1];
        const float4 b0 = bp[f4 * 2],     b1 = bp[f4 * 2 + 1];
        const __half2* h = (const __half2*)&v[i];
        float2 f0 = __half22float2(h[0]), f1 = __half22float2(h[1]);
        float2 f2 = __half22float2(h[2]), f3 = __half22float2(h[3]);
        float4 out;
        __half2* oh = (__half2*)&out;
        oh[0] = __floats2half2_rn((f0.x - mean) * rstd * w0.x + b0.x,
                                  (f0.y - mean) * rstd * w0.y + b0.y);
        oh[1] = __floats2half2_rn((f1.x - mean) * rstd * w0.z + b0.z,
                                  (f1.y - mean) * rstd * w0.w + b0.w);
        oh[2] = __floats2half2_rn((f2.x - mean) * rstd * w1.x + b1.x,
                                  (f2.y - mean) * rstd * w1.y + b1.y);
        oh[3] = __floats2half2_rn((f3.x - mean) * rstd * w1.z + b1.z,
                                  (f3.y - mean) * rstd * w1.w + b1.w);
        p4[f4] = out;
    }
}

// ---------------------------------------------------------------------------
// Attention: q len 1 over 2x2 key patch. fp16 in/out, fp32 math.
// ---------------------------------------------------------------------------
__global__ void attn_kernel(const __half* __restrict__ qh, const __half* __restrict__ kh,
                            const __half* __restrict__ vh, __half* __restrict__ o)
{
    const int r  = blockIdx.x;
    const int n  = r / NQ_TOK;
    const int qi = r - n * NQ_TOK;
    const int ar = qi / 12;
    const int ac = qi - ar * 12;
    const int head = threadIdx.x >> 5, lane = threadIdx.x & 31;
    const size_t qoff = (size_t)r * E_DIM + head * 128 + lane * 4;
    const __half2* qp = (const __half2*)(qh + qoff);
    const float2 q0 = __half22float2(qp[0]), q1 = __half22float2(qp[1]);

    int trow[4];
    #pragma unroll
    for (int j = 0; j < 4; j++)
        trow[j] = n * TN_TOK + (2 * ar + (j >> 1)) * 24 + (2 * ac + (j & 1));

    float s[4];
    #pragma unroll
    for (int j = 0; j < 4; j++) {
        const __half2* kp = (const __half2*)(kh + (size_t)trow[j] * E_DIM + head * 128 + lane * 4);
        const float2 k0 = __half22float2(kp[0]), k1 = __half22float2(kp[1]);
        float d = q0.x * k0.x + q0.y * k0.y + q1.x * k1.x + q1.y * k1.y;
        #pragma unroll
        for (int off = 16; off; off >>= 1) d += __shfl_xor_sync(0xffffffffu, d, off);
        s[j] = d * 0.08838834764831843f;
    }
    const float m = fmaxf(fmaxf(s[0], s[1]), fmaxf(s[2], s[3]));
    float e[4], tot = 0.0f;
    #pragma unroll
    for (int j = 0; j < 4; j++) { e[j] = expf(s[j] - m); tot += e[j]; }
    const float inv = 1.0f / tot;

    float a0 = 0.f, a1 = 0.f, a2 = 0.f, a3 = 0.f;
    #pragma unroll
    for (int j = 0; j < 4; j++) {
        const float pj = e[j] * inv;
        const __half2* vp = (const __half2*)(vh + (size_t)trow[j] * E_DIM + head * 128 + lane * 4);
        const float2 v0 = __half22float2(vp[0]), v1 = __half22float2(vp[1]);
        a0 += pj * v0.x; a1 += pj * v0.y; a2 += pj * v1.x; a3 += pj * v1.y;
    }
    __half2* op = (__half2*)(o + qoff);
    op[0] = __floats2half2_rn(a0, a1);
    op[1] = __floats2half2_rn(a2, a3);
}

// ---------------------------------------------------------------------------
extern "C" void kernel_launch(void* const* d_in, const int* in_sizes, int n_in,
                              void* d_out, int out_size)
{
    const float* x      = (const float*)d_in[0];
    const float* x_feat = (const float*)d_in[1];
    const float* w_q    = (const float*)d_in[2];
    const float* w_k1   = (const float*)d_in[3];
    const float* b_k1   = (const float*)d_in[4];
    const float* w_k2   = (const float*)d_in[5];
    const float* b_k2   = (const float*)d_in[6];
    const float* w_v1   = (const float*)d_in[7];
    const float* b_v1   = (const float*)d_in[8];
    const float* w_v2   = (const float*)d_in[9];
    const float* b_v2   = (const float*)d_in[10];
    const float* ln_q_w = (const float*)d_in[11];
    const float* ln_q_b = (const float*)d_in[12];
    const float* ln_k_w = (const float*)d_in[13];
    const float* ln_k_b = (const float*)d_in[14];
    const float* ln_v_w = (const float*)d_in[15];
    const float* ln_v_b = (const float*)d_in[16];
    const float* in_w   = (const float*)d_in[17];
    const float* in_b   = (const float*)d_in[18];
    const float* out_w  = (const float*)d_in[19];
    const float* out_b  = (const float*)d_in[20];

    __half *h2, *key, *val, *kh, *vh, *qb, *qh, *o, *xr, *xfr, *wt;
    float* bcat;
    cudaGetSymbolAddress((void**)&h2,  g_h2);
    cudaGetSymbolAddress((void**)&key, g_key);
    cudaGetSymbolAddress((void**)&val, g_val);
    cudaGetSymbolAddress((void**)&kh,  g_kh);
    cudaGetSymbolAddress((void**)&vh,  g_vh);
    cudaGetSymbolAddress((void**)&qb,  g_q);
    cudaGetSymbolAddress((void**)&qh,  g_qh);
    cudaGetSymbolAddress((void**)&o,   g_o);
    cudaGetSymbolAddress((void**)&xr,  g_xr);
    cudaGetSymbolAddress((void**)&xfr, g_xfr);
    cudaGetSymbolAddress((void**)&wt,  g_wt);
    cudaGetSymbolAddress((void**)&bcat, g_bcat);

    __half* wt_kv1 = wt;                    // [w_k1 ; w_v1]
    __half* wt_k2  = wt + 2 * (size_t)MW;   // wt_v2 contiguous at +MW
    __half* wt_q   = wt + 4 * (size_t)MW;
    __half* wt_in  = wt + 5 * (size_t)MW;   // wqh | wkh | wvh
    __half* wt_out = wt + 8 * (size_t)MW;

    const int smem_bytes = STAGES * STAGE_B;  // 110592
    cudaFuncSetAttribute(gemm_f16<0, 0>, cudaFuncAttributeMaxDynamicSharedMemorySize, smem_bytes);
    cudaFuncSetAttribute(gemm_f16<1, 0>, cudaFuncAttributeMaxDynamicSharedMemorySize, smem_bytes);
    cudaFuncSetAttribute(gemm_f16<0, 1>, cudaFuncAttributeMaxDynamicSharedMemorySize, smem_bytes);

    // launch 1: merged conversion prepass
    {
        ConvJobs jobs;
        jobs.j[0] = { (const float4*)x,      (__half2*)xr,      M_SMALL * E_DIM / 4 };
        jobs.j[1] = { (const float4*)x_feat, (__half2*)xfr,     M_BIG   * E_DIM / 4 };
        jobs.j[2] = { (const float4*)w_k1,   (__half2*)wt_kv1,  MW / 4 };
        jobs.j[3] = { (const float4*)w_v1,   (__half2*)(wt_kv1 + MW), MW / 4 };
        jobs.j[4] = { (const float4*)w_k2,   (__half2*)wt_k2,   MW / 4 };
        jobs.j[5] = { (const float4*)w_v2,   (__half2*)(wt_k2 + MW), MW / 4 };
        jobs.j[6] = { (const float4*)w_q,    (__half2*)wt_q,    MW / 4 };
        jobs.j[7] = { (const float4*)in_w,   (__half2*)wt_in,   3 * MW / 4 };
        jobs.j[8] = { (const float4*)out_w,  (__half2*)wt_out,  MW / 4 };
        conv_all_kernel<<<dim3(4096, 9), 256>>>(jobs);
    }
    // launch 2: bias concat
    bias_concat_kernel<<<8, 256>>>(b_k1, b_v1, bcat);

    const dim3 blk(256);
    const dim3 gKV(16, M_BIG / BM, 1);      // (16, 288): KV1, N=2048
    const dim3 gBig2(8, M_BIG / BM, 2);     // (8, 288, 2): dual big GEMM
    const dim3 gSm(8, M_SMALL / BM, 1);     // (8, 72)

    // launch 3: merged K1+V1 (gelu) -> h2 [M_BIG x 2048]
    gemm_f16<1, 0><<<gKV, blk, smem_bytes>>>(xfr, xfr, E_DIM, wt_kv1, bcat, bcat, h2, h2, 2048);
    // launch 4 (ncu capture slot): K2 (z=0) + V2 (z=1) merged
    gemm_f16<0, 0><<<gBig2, blk, smem_bytes>>>(h2, h2 + 1024, 2048, wt_k2,
                                               b_k2, b_v2, key, val, E_DIM);
    // launch 5: qb = x @ w_q^T (no bias)
    gemm_f16<0, 0><<<gSm, blk, smem_bytes>>>(xr, xr, E_DIM, wt_q, nullptr, nullptr, qb, qb, E_DIM);
    // launch 6: single 3-job warp-per-row LN (key, val, qb)
    {
        LnJobs lj = {};
        lj.d[0] = key; lj.w[0] = ln_k_w; lj.b[0] = ln_k_b; lj.rows[0] = M_BIG;
        lj.d[1] = val; lj.w[1] = ln_v_w; lj.b[1] = ln_v_b; lj.rows[1] = M_BIG;
        lj.d[2] = qb;  lj.w[2] = ln_q_w; lj.b[2] = ln_q_b; lj.rows[2] = M_SMALL;
        ln3_kernel<<<(2 * M_BIG + M_SMALL) / 8, 256>>>(lj);
    }
    // launch 7: in_proj qh (small)
    gemm_f16<0, 0><<<gSm, blk, smem_bytes>>>(qb, qb, E_DIM, wt_in, in_b, in_b, qh, qh, E_DIM);
    // launch 8: in_proj kh (z=0) + vh (z=1) merged
    gemm_f16<0, 0><<<gBig2, blk, smem_bytes>>>(key, val, E_DIM, wt_in + MW,
                                               in_b + 1024, in_b + 2048, kh, vh, E_DIM);
    // launch 9: attention
    attn_kernel<<<M_SMALL, 256>>>(qh, kh, vh, o);
    // launch 10: out_proj -> d_out (float)
    gemm_f16<0, 1><<<gSm, blk, smem_bytes>>>(o, o, E_DIM, wt_out, out_b, out_b,
                                             d_out, d_out, E_DIM);
}